// round 16
// baseline (speedup 1.0000x reference)
#include <cuda_runtime.h>
#include <cuda_fp16.h>
#include <cstdint>
#include <math.h>

// ---------------- problem constants ----------------
#define TT       2048
#define BB       32
#define NTOK     (TT*BB)        // 65536
#define DM       512
#define NH       8
#define DH       64
#define DFF      2048
#define NCLS     64
#define EVAL     256
#define DPE      256
#define NLAYERS  2

// ---------------- scratch buffers ----------------
__device__ float  g_H[(size_t)NTOK * DM];
__device__ __half g_Hh[(size_t)NTOK * DM];
__device__ __half g_Qh[(size_t)NTOK * DM];
__device__ __half g_Kh[(size_t)NTOK * DM];
__device__ __half g_Vh[(size_t)NTOK * DM];
__device__ __half g_Th[(size_t)NTOK * DM];
__device__ __half g_Ah[(size_t)NTOK * DM];
__device__ __half g_Fh[(size_t)NTOK * DFF];
__device__ __half g_Wqh[NLAYERS * DM * DM];
__device__ __half g_Wkh[NLAYERS * DM * DM];
__device__ __half g_Wvh[NLAYERS * DM * DM];
__device__ __half g_Woh[NLAYERS * DM * DM];
__device__ __half g_W1h[NLAYERS * DM * DFF];
__device__ __half g_W2h[NLAYERS * DFF * DM];
__device__ __half g_Wph[DM * NCLS];

// ---------------- fp32 -> fp16 weight conversion (merged launches) ----------------
__device__ __forceinline__ void f2h_body(const float4* src, __half2* dst, int i)
{
    float4 v = src[i];
    dst[2 * i]     = __floats2half2_rn(v.x, v.y);
    dst[2 * i + 1] = __floats2half2_rn(v.z, v.w);
}

__global__ void f2h_a(const float* Wq, const float* Wk, const float* Wv, const float* Wo,
                      __half* dq, __half* dk, __half* dv, __half* do_)
{
    int i = blockIdx.x * 256 + threadIdx.x;
    const float* s; __half* d;
    switch (blockIdx.z) {
        case 0: s = Wq; d = dq;  break;
        case 1: s = Wk; d = dk;  break;
        case 2: s = Wv; d = dv;  break;
        default: s = Wo; d = do_; break;
    }
    f2h_body((const float4*)s, (__half2*)d, i);
}

__global__ void f2h_b(const float* W1, const float* W2, const float* Wp,
                      __half* d1, __half* d2, __half* dp)
{
    int i = blockIdx.x * 256 + threadIdx.x;
    const float* s; __half* d; int n4;
    switch (blockIdx.z) {
        case 0: s = W1; d = d1; n4 = NLAYERS * DM * DFF / 4; break;
        case 1: s = W2; d = d2; n4 = NLAYERS * DFF * DM / 4; break;
        default: s = Wp; d = dp; n4 = DM * NCLS / 4; break;
    }
    if (i < n4) f2h_body((const float4*)s, (__half2*)d, i);
}

// ---------------- embed + positional encoding ----------------
__global__ void embed_kernel(const int* __restrict__ x, const float* __restrict__ E,
                             float* __restrict__ H, __half* __restrict__ Hh)
{
    int idx = blockIdx.x * 256 + threadIdx.x;
    int d = idx & (DM - 1);
    int n = idx >> 9;
    float v;
    if (d < EVAL) {
        int cls = x[n];
        v = E[cls * EVAL + d];
    } else {
        int p = d - EVAL;
        int j = p >> 1;
        const float c = (float)(-9.210340371976184 / 256.0);
        float freq = expf((float)(2 * j) * c);
        float ang  = (float)(n >> 5) * freq;
        v = (p & 1) ? cosf(ang) : sinf(ang);
    }
    H[idx] = v;
    Hh[idx] = __float2half_rn(v);
}

// ---------------- tensor-core HGEMM (round-15 winner + upfront dual-ks fragment load) ----------------
__device__ __forceinline__ uint32_t smem_u32(const void* p) {
    return (uint32_t)__cvta_generic_to_shared(p);
}
__device__ __forceinline__ void ldsm_x4(uint32_t addr, uint32_t& r0, uint32_t& r1,
                                        uint32_t& r2, uint32_t& r3) {
    asm volatile("ldmatrix.sync.aligned.m8n8.x4.shared.b16 {%0,%1,%2,%3},[%4];\n"
                 : "=r"(r0), "=r"(r1), "=r"(r2), "=r"(r3) : "r"(addr));
}
__device__ __forceinline__ void ldsm_x4t(uint32_t addr, uint32_t& r0, uint32_t& r1,
                                         uint32_t& r2, uint32_t& r3) {
    asm volatile("ldmatrix.sync.aligned.m8n8.x4.trans.shared.b16 {%0,%1,%2,%3},[%4];\n"
                 : "=r"(r0), "=r"(r1), "=r"(r2), "=r"(r3) : "r"(addr));
}
__device__ __forceinline__ void mma16816(float* d, const uint32_t* a, uint32_t b0, uint32_t b1) {
    asm volatile("mma.sync.aligned.m16n8k16.row.col.f32.f16.f16.f32 "
                 "{%0,%1,%2,%3},{%4,%5,%6,%7},{%8,%9},{%0,%1,%2,%3};\n"
                 : "+f"(d[0]), "+f"(d[1]), "+f"(d[2]), "+f"(d[3])
                 : "r"(a[0]), "r"(a[1]), "r"(a[2]), "r"(a[3]), "r"(b0), "r"(b1));
}
__device__ __forceinline__ void cpa16(uint32_t dst, const void* src, int srcBytes) {
    asm volatile("cp.async.cg.shared.global [%0], [%1], 16, %2;\n"
                 :: "r"(dst), "l"(src), "r"(srcBytes));
}
__device__ __forceinline__ void cp_commit() {
    asm volatile("cp.async.commit_group;\n");
}
__device__ __forceinline__ void cp_wait1() {
    asm volatile("cp.async.wait_group 1;\n");
}

template<int ACT>
__device__ __forceinline__ float act_apply(float v) {
    if (ACT == 1) return (v > 0.f) ? (v + 1.f) : expf(v);
    if (ACT == 2) return fmaxf(v, 0.f);
    return v;
}

#define APITCH 40
#define BPITCH 136
#define STAGES 3

// TRANS=1: C32 is [B,T,N] and row gm = t*BB+b is scattered to (b,t).
template<int ACT, int WF32, int WF16, int TRANS>
__global__ __launch_bounds__(256)
void hgemm(const __half* __restrict__ A, const __half* __restrict__ W,
           const float* __restrict__ bias, float* __restrict__ C32,
           __half* __restrict__ C16, int M, int N, int K)
{
    __shared__ __half As[STAGES][128 * APITCH];
    __shared__ __half Bs[STAGES][32 * BPITCH];

    const int tid = threadIdx.x;
    const int bm = blockIdx.y, bn = blockIdx.x;
    const int wid = tid >> 5, lane = tid & 31;
    const int wm = wid >> 2, wn = wid & 3;

    float acc[4][4][4];
#pragma unroll
    for (int i = 0; i < 4; i++)
#pragma unroll
        for (int j = 0; j < 4; j++)
#pragma unroll
            for (int r = 0; r < 4; r++) acc[i][j][r] = 0.f;

    const int aRow = tid >> 1, aCol = (tid & 1) * 16;
    const __half* Ag = A + (size_t)(bm * 128 + aRow) * K + aCol;
    const int bRow = tid >> 3, bCol = (tid & 7) * 16;
    const int gnB = bn * 128 + bCol;
    const __half* Wg = W + (size_t)bRow * N + gnB;
    const int bPred = (gnB < N) ? 16 : 0;

    const uint32_t aDst0 = smem_u32(&As[0][aRow * APITCH + aCol]);
    const uint32_t bDst0 = smem_u32(&Bs[0][bRow * BPITCH + bCol]);
    const uint32_t aStg = 128 * APITCH * 2;
    const uint32_t bStg = 32 * BPITCH * 2;

    const int ktiles = K >> 5;

#define LOAD_STAGE(kt, s)                                                     \
    do {                                                                      \
        const __half* ag_ = Ag + ((kt) << 5);                                 \
        cpa16(aDst0 + (s) * aStg,      ag_,     16);                          \
        cpa16(aDst0 + (s) * aStg + 16, ag_ + 8, 16);                          \
        const __half* wg_ = Wg + (size_t)((kt) << 5) * N;                     \
        cpa16(bDst0 + (s) * bStg,      wg_,     bPred);                       \
        cpa16(bDst0 + (s) * bStg + 16, wg_ + 8, bPred);                       \
    } while (0)

    LOAD_STAGE(0, 0); cp_commit();
    LOAD_STAGE(1, 1); cp_commit();

    const uint32_t aBase = smem_u32(As) + (uint32_t)((wm * 64 + (lane & 15)) * APITCH + (lane >> 4) * 8) * 2;
    const uint32_t bBase = smem_u32(Bs) + (uint32_t)((lane & 15) * BPITCH + wn * 32 + (lane >> 4) * 8) * 2;

    int s = 0;
    for (int kt = 0; kt < ktiles; kt++) {
        cp_wait1();
        __syncthreads();

        if (kt + 2 < ktiles) {
            int sn = (s + 2 >= STAGES) ? (s + 2 - STAGES) : (s + 2);
            LOAD_STAGE(kt + 2, sn);
        }
        cp_commit();

        const uint32_t aS = aBase + s * aStg;
        const uint32_t bS = bBase + s * bStg;

        // hoist ALL fragment loads for both ks phases: one exposed ldsm
        // latency per k-tile, then 32 uninterrupted HMMA.
        uint32_t a[2][4][4], b[2][2][4];
#pragma unroll
        for (int ks = 0; ks < 2; ks++) {
#pragma unroll
            for (int mt = 0; mt < 4; mt++)
                ldsm_x4(aS + (uint32_t)(mt * 16 * APITCH + ks * 16) * 2,
                        a[ks][mt][0], a[ks][mt][1], a[ks][mt][2], a[ks][mt][3]);
#pragma unroll
            for (int nt = 0; nt < 2; nt++)
                ldsm_x4t(bS + (uint32_t)(ks * 16 * BPITCH + nt * 16) * 2,
                         b[ks][nt][0], b[ks][nt][1], b[ks][nt][2], b[ks][nt][3]);
        }
#pragma unroll
        for (int ks = 0; ks < 2; ks++) {
#pragma unroll
            for (int mt = 0; mt < 4; mt++) {
#pragma unroll
                for (int nt = 0; nt < 2; nt++) {
                    mma16816(acc[mt][nt * 2],     a[ks][mt], b[ks][nt][0], b[ks][nt][1]);
                    mma16816(acc[mt][nt * 2 + 1], a[ks][mt], b[ks][nt][2], b[ks][nt][3]);
                }
            }
        }
        s = (s + 1 >= STAGES) ? 0 : (s + 1);
    }
#undef LOAD_STAGE

    const int gr = lane >> 2, tg = lane & 3;
#pragma unroll
    for (int mt = 0; mt < 4; mt++) {
        const int gm0 = bm * 128 + wm * 64 + mt * 16 + gr;
#pragma unroll
        for (int n8 = 0; n8 < 4; n8++) {
            const int gn = bn * 128 + wn * 32 + n8 * 8 + tg * 2;
            if (gn < N) {
                float b0 = bias[gn], b1 = bias[gn + 1];
                float* ac = acc[mt][n8];
                float v00 = act_apply<ACT>(ac[0] + b0);
                float v01 = act_apply<ACT>(ac[1] + b1);
                float v10 = act_apply<ACT>(ac[2] + b0);
                float v11 = act_apply<ACT>(ac[3] + b1);
                if (WF32) {
                    if (TRANS) {
                        const int gm1 = gm0 + 8;
                        size_t o0 = ((size_t)(gm0 & (BB - 1)) * TT + (gm0 >> 5)) * N + gn;
                        size_t o1 = ((size_t)(gm1 & (BB - 1)) * TT + (gm1 >> 5)) * N + gn;
                        C32[o0]     = v00;
                        C32[o0 + 1] = v01;
                        C32[o1]     = v10;
                        C32[o1 + 1] = v11;
                    } else {
                        C32[(size_t)gm0 * N + gn]           = v00;
                        C32[(size_t)gm0 * N + gn + 1]       = v01;
                        C32[(size_t)(gm0 + 8) * N + gn]     = v10;
                        C32[(size_t)(gm0 + 8) * N + gn + 1] = v11;
                    }
                }
                if (WF16) {
                    *(__half2*)&C16[(size_t)gm0 * N + gn]       = __floats2half2_rn(v00, v01);
                    *(__half2*)&C16[(size_t)(gm0 + 8) * N + gn] = __floats2half2_rn(v10, v11);
                }
            }
        }
    }
}

// ---------------- causal linear-attention scan, 8-step batched ----------------
__global__ __launch_bounds__(64)
void scan_kernel(const __half* __restrict__ Q, const __half* __restrict__ K,
                 const __half* __restrict__ V, __half* __restrict__ A)
{
    const int bh = blockIdx.x;
    const int b  = bh >> 3, h = bh & 7;
    const int m  = threadIdx.x;

    __shared__ float q_sh[8][64], k_sh[8][64], z_sh[64];

    float S[64];
#pragma unroll
    for (int d = 0; d < 64; d++) S[d] = 0.f;
    z_sh[m] = 0.f;

    const size_t stride = (size_t)BB * DM;
    const size_t base = (size_t)b * DM + h * 64 + m;

    float q[8], k[8], v[8];
#pragma unroll
    for (int s = 0; s < 8; s++) {
        size_t i = base + (size_t)s * stride;
        q[s] = __half2float(Q[i]);
        k[s] = __half2float(K[i]);
        v[s] = __half2float(V[i]);
    }

    for (int t0 = 0; t0 < TT; t0 += 8) {
#pragma unroll
        for (int s = 0; s < 8; s++) {
            q_sh[s][m] = q[s];
            k_sh[s][m] = k[s];
        }
        __syncthreads();

        float qn[8], kn[8], vn[8];
        if (t0 + 8 < TT) {
#pragma unroll
            for (int s = 0; s < 8; s++) {
                size_t i = base + (size_t)(t0 + 8 + s) * stride;
                qn[s] = __half2float(Q[i]);
                kn[s] = __half2float(K[i]);
                vn[s] = __half2float(V[i]);
            }
        }

        float num[8][2], den[8][2];
#pragma unroll
        for (int s = 0; s < 8; s++) {
            num[s][0] = 0.f; num[s][1] = 0.f;
            den[s][0] = 0.f; den[s][1] = 0.f;
        }

#pragma unroll 2
        for (int d0 = 0; d0 < 64; d0 += 4) {
            float4 zv = *(const float4*)&z_sh[d0];
            float zz[4] = { zv.x, zv.y, zv.z, zv.w };
#pragma unroll
            for (int s = 0; s < 8; s++) {
                float4 kk = *(const float4*)&k_sh[s][d0];
                float4 qq = *(const float4*)&q_sh[s][d0];
                const float* kf = (const float*)&kk;
                const float* qf = (const float*)&qq;
#pragma unroll
                for (int j = 0; j < 4; j++) {
                    const int d = d0 + j;
                    zz[j] += kf[j];
                    den[s][j & 1] = fmaf(qf[j], zz[j], den[s][j & 1]);
                    S[d] = fmaf(kf[j], v[s], S[d]);
                    num[s][j & 1] = fmaf(qf[j], S[d], num[s][j & 1]);
                }
            }
        }
        __syncthreads();

        z_sh[m] += ((k[0] + k[1]) + (k[2] + k[3])) + ((k[4] + k[5]) + (k[6] + k[7]));

#pragma unroll
        for (int s = 0; s < 8; s++) {
            float n  = num[s][0] + num[s][1];
            float dd = den[s][0] + den[s][1] + 1e-6f;
            A[base + (size_t)(t0 + s) * stride] = __float2half_rn(n / dd);
        }

#pragma unroll
        for (int s = 0; s < 8; s++) { q[s] = qn[s]; k[s] = kn[s]; v[s] = vn[s]; }
    }
}

// ---------------- fused residual + LayerNorm (fp16 residual branch) ----------------
__global__ __launch_bounds__(128)
void add_ln_kernel(float* __restrict__ H, __half* __restrict__ Hh,
                   const __half* __restrict__ R,
                   const float* __restrict__ g, const float* __restrict__ be)
{
    __shared__ float sh[4];
    const int n = blockIdx.x, tid = threadIdx.x;
    const size_t base = (size_t)n * DM;

    float x[4];
    float s = 0.f;
#pragma unroll
    for (int i = 0; i < 4; i++) {
        int d = tid + 128 * i;
        x[i] = H[base + d] + __half2float(R[base + d]);
        s += x[i];
    }
#pragma unroll
    for (int o = 16; o > 0; o >>= 1) s += __shfl_xor_sync(0xffffffffu, s, o);
    if ((tid & 31) == 0) sh[tid >> 5] = s;
    __syncthreads();
    float mean = (sh[0] + sh[1] + sh[2] + sh[3]) * (1.f / 512.f);
    __syncthreads();

    float vs = 0.f;
#pragma unroll
    for (int i = 0; i < 4; i++) { float dl = x[i] - mean; vs += dl * dl; }
#pragma unroll
    for (int o = 16; o > 0; o >>= 1) vs += __shfl_xor_sync(0xffffffffu, vs, o);
    if ((tid & 31) == 0) sh[tid >> 5] = vs;
    __syncthreads();
    float var = (sh[0] + sh[1] + sh[2] + sh[3]) * (1.f / 512.f);
    float inv = rsqrtf(var + 1e-5f);

#pragma unroll
    for (int i = 0; i < 4; i++) {
        int d = tid + 128 * i;
        float v = fmaf((x[i] - mean) * inv, g[d], be[d]);
        H[base + d] = v;
        Hh[base + d] = __float2half_rn(v);
    }
}

// ---------------- orchestration ----------------
extern "C" void kernel_launch(void* const* d_in, const int* in_sizes, int n_in,
                              void* d_out, int out_size)
{
    (void)in_sizes; (void)n_in; (void)out_size;
    const int*   x   = (const int*)d_in[0];
    const float* E   = (const float*)d_in[1];
    const float* Wq  = (const float*)d_in[2];  const float* bq  = (const float*)d_in[3];
    const float* Wk  = (const float*)d_in[4];  const float* bk  = (const float*)d_in[5];
    const float* Wv  = (const float*)d_in[6];  const float* bv  = (const float*)d_in[7];
    const float* Wo  = (const float*)d_in[8];  const float* bo  = (const float*)d_in[9];
    const float* g1  = (const float*)d_in[10]; const float* be1 = (const float*)d_in[11];
    const float* W1  = (const float*)d_in[12]; const float* b1  = (const float*)d_in[13];
    const float* W2  = (const float*)d_in[14]; const float* b2  = (const float*)d_in[15];
    const float* g2  = (const float*)d_in[16]; const float* be2 = (const float*)d_in[17];
    const float* Wp  = (const float*)d_in[18]; const float* bp  = (const float*)d_in[19];
    float* out = (float*)d_out;

    float  *pH;
    __half *pHh, *pQh, *pKh, *pVh, *pTh, *pAh, *pFh;
    __half *pWqh, *pWkh, *pWvh, *pWoh, *pW1h, *pW2h, *pWph;
    cudaGetSymbolAddress((void**)&pH,  g_H);
    cudaGetSymbolAddress((void**)&pHh, g_Hh);
    cudaGetSymbolAddress((void**)&pQh, g_Qh);
    cudaGetSymbolAddress((void**)&pKh, g_Kh);
    cudaGetSymbolAddress((void**)&pVh, g_Vh);
    cudaGetSymbolAddress((void**)&pTh, g_Th);
    cudaGetSymbolAddress((void**)&pAh, g_Ah);
    cudaGetSymbolAddress((void**)&pFh, g_Fh);
    cudaGetSymbolAddress((void**)&pWqh, g_Wqh);
    cudaGetSymbolAddress((void**)&pWkh, g_Wkh);
    cudaGetSymbolAddress((void**)&pWvh, g_Wvh);
    cudaGetSymbolAddress((void**)&pWoh, g_Woh);
    cudaGetSymbolAddress((void**)&pW1h, g_W1h);
    cudaGetSymbolAddress((void**)&pW2h, g_W2h);
    cudaGetSymbolAddress((void**)&pWph, g_Wph);

    f2h_a<<<dim3(NLAYERS * DM * DM / 4 / 256, 1, 4), 256>>>(Wq, Wk, Wv, Wo,
                                                            pWqh, pWkh, pWvh, pWoh);
    f2h_b<<<dim3(NLAYERS * DM * DFF / 4 / 256, 1, 3), 256>>>(W1, W2, Wp, pW1h, pW2h, pWph);

    embed_kernel<<<(NTOK * DM) / 256, 256>>>(x, E, pH, pHh);

    const dim3 gDM(DM / 128, NTOK / 128);     // (4, 512)
    const dim3 gFF(DFF / 128, NTOK / 128);    // (16, 512)
    const dim3 gP(1, NTOK / 128);             // (1, 512)

    for (int l = 0; l < NLAYERS; l++) {
        const size_t wOff  = (size_t)l * DM * DM;
        const size_t bOff  = (size_t)l * DM;
        const size_t w1Off = (size_t)l * DM * DFF;
        const size_t b1Off = (size_t)l * DFF;
        const size_t w2Off = (size_t)l * DFF * DM;

        hgemm<1,0,1,0><<<gDM, 256>>>(pHh, pWqh + wOff, bq + bOff, (float*)0, pQh, NTOK, DM, DM);
        hgemm<1,0,1,0><<<gDM, 256>>>(pHh, pWkh + wOff, bk + bOff, (float*)0, pKh, NTOK, DM, DM);
        hgemm<0,0,1,0><<<gDM, 256>>>(pHh, pWvh + wOff, bv + bOff, (float*)0, pVh, NTOK, DM, DM);

        scan_kernel<<<BB * NH, 64>>>(pQh, pKh, pVh, pAh);

        hgemm<0,0,1,0><<<gDM, 256>>>(pAh, pWoh + wOff, bo + bOff, (float*)0, pTh, NTOK, DM, DM);
        add_ln_kernel<<<NTOK, 128>>>(pH, pHh, pTh, g1 + bOff, be1 + bOff);

        hgemm<2,0,1,0><<<gFF, 256>>>(pHh, pW1h + w1Off, b1 + b1Off, (float*)0, pFh, NTOK, DFF, DM);
        hgemm<0,0,1,0><<<gDM, 256>>>(pFh, pW2h + w2Off, b2 + bOff, (float*)0, pTh, NTOK, DM, DFF);
        add_ln_kernel<<<NTOK, 128>>>(pH, pHh, pTh, g2 + bOff, be2 + bOff);
    }

    hgemm<0,1,0,1><<<gP, 256>>>(pHh, pWph, bp, out, (__half*)0, NTOK, NCLS, DM);
}

// round 17
// speedup vs baseline: 1.0987x; 1.0987x over previous
#include <cuda_runtime.h>
#include <cuda_fp16.h>
#include <cstdint>
#include <math.h>

// ---------------- problem constants ----------------
#define TT       2048
#define BB       32
#define NTOK     (TT*BB)        // 65536
#define DM       512
#define NH       8
#define DH       64
#define DFF      2048
#define NCLS     64
#define EVAL     256
#define DPE      256
#define NLAYERS  2

// ---------------- scratch buffers ----------------
__device__ float  g_H[(size_t)NTOK * DM];
__device__ __half g_Hh[(size_t)NTOK * DM];
__device__ __half g_Qh[(size_t)NTOK * DM];
__device__ __half g_Kh[(size_t)NTOK * DM];
__device__ __half g_Vh[(size_t)NTOK * DM];
__device__ __half g_Th[(size_t)NTOK * DM];
__device__ __half g_Ah[(size_t)NTOK * DM];
__device__ __half g_Fh[(size_t)NTOK * DFF];
__device__ __half g_Wqh[NLAYERS * DM * DM];
__device__ __half g_Wkh[NLAYERS * DM * DM];
__device__ __half g_Wvh[NLAYERS * DM * DM];
__device__ __half g_Woh[NLAYERS * DM * DM];
__device__ __half g_W1h[NLAYERS * DM * DFF];
__device__ __half g_W2h[NLAYERS * DFF * DM];
__device__ __half g_Wph[DM * NCLS];

// ---------------- fp32 -> fp16 weight conversion (merged launches) ----------------
__device__ __forceinline__ void f2h_body(const float4* src, __half2* dst, int i)
{
    float4 v = src[i];
    dst[2 * i]     = __floats2half2_rn(v.x, v.y);
    dst[2 * i + 1] = __floats2half2_rn(v.z, v.w);
}

__global__ void f2h_a(const float* Wq, const float* Wk, const float* Wv, const float* Wo,
                      __half* dq, __half* dk, __half* dv, __half* do_)
{
    int i = blockIdx.x * 256 + threadIdx.x;
    const float* s; __half* d;
    switch (blockIdx.z) {
        case 0: s = Wq; d = dq;  break;
        case 1: s = Wk; d = dk;  break;
        case 2: s = Wv; d = dv;  break;
        default: s = Wo; d = do_; break;
    }
    f2h_body((const float4*)s, (__half2*)d, i);
}

__global__ void f2h_b(const float* W1, const float* W2, const float* Wp,
                      __half* d1, __half* d2, __half* dp)
{
    int i = blockIdx.x * 256 + threadIdx.x;
    const float* s; __half* d; int n4;
    switch (blockIdx.z) {
        case 0: s = W1; d = d1; n4 = NLAYERS * DM * DFF / 4; break;
        case 1: s = W2; d = d2; n4 = NLAYERS * DFF * DM / 4; break;
        default: s = Wp; d = dp; n4 = DM * NCLS / 4; break;
    }
    if (i < n4) f2h_body((const float4*)s, (__half2*)d, i);
}

// ---------------- embed + positional encoding ----------------
__global__ void embed_kernel(const int* __restrict__ x, const float* __restrict__ E,
                             float* __restrict__ H, __half* __restrict__ Hh)
{
    int idx = blockIdx.x * 256 + threadIdx.x;
    int d = idx & (DM - 1);
    int n = idx >> 9;
    float v;
    if (d < EVAL) {
        int cls = x[n];
        v = E[cls * EVAL + d];
    } else {
        int p = d - EVAL;
        int j = p >> 1;
        const float c = (float)(-9.210340371976184 / 256.0);
        float freq = expf((float)(2 * j) * c);
        float ang  = (float)(n >> 5) * freq;
        v = (p & 1) ? cosf(ang) : sinf(ang);
    }
    H[idx] = v;
    Hh[idx] = __float2half_rn(v);
}

// ---------------- tensor-core HGEMM ----------------
// 512 threads/CTA, 16 warps of 32x32 tiles (4x4), 128x128 CTA tile.
// Same smem layout / 3-stage cp.async / wait_group 1 as the proven kernel.
__device__ __forceinline__ uint32_t smem_u32(const void* p) {
    return (uint32_t)__cvta_generic_to_shared(p);
}
__device__ __forceinline__ void ldsm_x4(uint32_t addr, uint32_t& r0, uint32_t& r1,
                                        uint32_t& r2, uint32_t& r3) {
    asm volatile("ldmatrix.sync.aligned.m8n8.x4.shared.b16 {%0,%1,%2,%3},[%4];\n"
                 : "=r"(r0), "=r"(r1), "=r"(r2), "=r"(r3) : "r"(addr));
}
__device__ __forceinline__ void ldsm_x4t(uint32_t addr, uint32_t& r0, uint32_t& r1,
                                         uint32_t& r2, uint32_t& r3) {
    asm volatile("ldmatrix.sync.aligned.m8n8.x4.trans.shared.b16 {%0,%1,%2,%3},[%4];\n"
                 : "=r"(r0), "=r"(r1), "=r"(r2), "=r"(r3) : "r"(addr));
}
__device__ __forceinline__ void mma16816(float* d, const uint32_t* a, uint32_t b0, uint32_t b1) {
    asm volatile("mma.sync.aligned.m16n8k16.row.col.f32.f16.f16.f32 "
                 "{%0,%1,%2,%3},{%4,%5,%6,%7},{%8,%9},{%0,%1,%2,%3};\n"
                 : "+f"(d[0]), "+f"(d[1]), "+f"(d[2]), "+f"(d[3])
                 : "r"(a[0]), "r"(a[1]), "r"(a[2]), "r"(a[3]), "r"(b0), "r"(b1));
}
__device__ __forceinline__ void cpa16(uint32_t dst, const void* src, int srcBytes) {
    asm volatile("cp.async.cg.shared.global [%0], [%1], 16, %2;\n"
                 :: "r"(dst), "l"(src), "r"(srcBytes));
}
__device__ __forceinline__ void cp_commit() {
    asm volatile("cp.async.commit_group;\n");
}
__device__ __forceinline__ void cp_wait1() {
    asm volatile("cp.async.wait_group 1;\n");
}

template<int ACT>
__device__ __forceinline__ float act_apply(float v) {
    if (ACT == 1) return (v > 0.f) ? (v + 1.f) : expf(v);
    if (ACT == 2) return fmaxf(v, 0.f);
    return v;
}

#define APITCH 40
#define BPITCH 136
#define STAGES 3

// TRANS=1: C32 is [B,T,N] and row gm = t*BB+b is scattered to (b,t).
template<int ACT, int WF32, int WF16, int TRANS>
__global__ __launch_bounds__(512, 2)
void hgemm(const __half* __restrict__ A, const __half* __restrict__ W,
           const float* __restrict__ bias, float* __restrict__ C32,
           __half* __restrict__ C16, int M, int N, int K)
{
    __shared__ __half As[STAGES][128 * APITCH];
    __shared__ __half Bs[STAGES][32 * BPITCH];

    const int tid = threadIdx.x;
    const int bm = blockIdx.y, bn = blockIdx.x;
    const int wid = tid >> 5, lane = tid & 31;
    const int wm = wid >> 2, wn = wid & 3;     // 4x4 warps, 32x32 tiles

    float acc[2][4][4];
#pragma unroll
    for (int i = 0; i < 2; i++)
#pragma unroll
        for (int j = 0; j < 4; j++)
#pragma unroll
            for (int r = 0; r < 4; r++) acc[i][j][r] = 0.f;

    // A: 128 rows x 32 halves = 512 x 16B chunks; 1 per thread
    const int aRow = tid >> 2, aCol = (tid & 3) * 8;
    const __half* Ag = A + (size_t)(bm * 128 + aRow) * K + aCol;
    // B: 32 rows x 128 halves = 512 x 16B chunks; 1 per thread
    const int bRow = tid >> 4, bCol = (tid & 15) * 8;
    const int gnB = bn * 128 + bCol;
    const __half* Wg = W + (size_t)bRow * N + gnB;
    const int bPred = (gnB < N) ? 16 : 0;

    const uint32_t aDst0 = smem_u32(&As[0][aRow * APITCH + aCol]);
    const uint32_t bDst0 = smem_u32(&Bs[0][bRow * BPITCH + bCol]);
    const uint32_t aStg = 128 * APITCH * 2;
    const uint32_t bStg = 32 * BPITCH * 2;

    const int ktiles = K >> 5;

#define LOAD_STAGE(kt, s)                                                     \
    do {                                                                      \
        cpa16(aDst0 + (s) * aStg, Ag + ((kt) << 5), 16);                      \
        cpa16(bDst0 + (s) * bStg, Wg + (size_t)((kt) << 5) * N, bPred);       \
    } while (0)

    LOAD_STAGE(0, 0); cp_commit();
    LOAD_STAGE(1, 1); cp_commit();

    const uint32_t aBase = smem_u32(As) + (uint32_t)((wm * 32 + (lane & 15)) * APITCH + (lane >> 4) * 8) * 2;
    const uint32_t bBase = smem_u32(Bs) + (uint32_t)((lane & 15) * BPITCH + wn * 32 + (lane >> 4) * 8) * 2;

    int s = 0;
    for (int kt = 0; kt < ktiles; kt++) {
        cp_wait1();
        __syncthreads();

        if (kt + 2 < ktiles) {
            int sn = (s + 2 >= STAGES) ? (s + 2 - STAGES) : (s + 2);
            LOAD_STAGE(kt + 2, sn);
        }
        cp_commit();

        const uint32_t aS = aBase + s * aStg;
        const uint32_t bS = bBase + s * bStg;
#pragma unroll
        for (int ks = 0; ks < 2; ks++) {
            uint32_t a[2][4], b[2][4];
#pragma unroll
            for (int mt = 0; mt < 2; mt++)
                ldsm_x4(aS + (uint32_t)(mt * 16 * APITCH + ks * 16) * 2,
                        a[mt][0], a[mt][1], a[mt][2], a[mt][3]);
#pragma unroll
            for (int nt = 0; nt < 2; nt++)
                ldsm_x4t(bS + (uint32_t)(ks * 16 * BPITCH + nt * 16) * 2,
                         b[nt][0], b[nt][1], b[nt][2], b[nt][3]);
#pragma unroll
            for (int mt = 0; mt < 2; mt++) {
#pragma unroll
                for (int nt = 0; nt < 2; nt++) {
                    mma16816(acc[mt][nt * 2],     a[mt], b[nt][0], b[nt][1]);
                    mma16816(acc[mt][nt * 2 + 1], a[mt], b[nt][2], b[nt][3]);
                }
            }
        }
        s = (s + 1 >= STAGES) ? 0 : (s + 1);
    }
#undef LOAD_STAGE

    const int gr = lane >> 2, tg = lane & 3;
#pragma unroll
    for (int mt = 0; mt < 2; mt++) {
        const int gm0 = bm * 128 + wm * 32 + mt * 16 + gr;
#pragma unroll
        for (int n8 = 0; n8 < 4; n8++) {
            const int gn = bn * 128 + wn * 32 + n8 * 8 + tg * 2;
            if (gn < N) {
                float b0 = bias[gn], b1 = bias[gn + 1];
                float* ac = acc[mt][n8];
                float v00 = act_apply<ACT>(ac[0] + b0);
                float v01 = act_apply<ACT>(ac[1] + b1);
                float v10 = act_apply<ACT>(ac[2] + b0);
                float v11 = act_apply<ACT>(ac[3] + b1);
                if (WF32) {
                    if (TRANS) {
                        const int gm1 = gm0 + 8;
                        size_t o0 = ((size_t)(gm0 & (BB - 1)) * TT + (gm0 >> 5)) * N + gn;
                        size_t o1 = ((size_t)(gm1 & (BB - 1)) * TT + (gm1 >> 5)) * N + gn;
                        C32[o0]     = v00;
                        C32[o0 + 1] = v01;
                        C32[o1]     = v10;
                        C32[o1 + 1] = v11;
                    } else {
                        C32[(size_t)gm0 * N + gn]           = v00;
                        C32[(size_t)gm0 * N + gn + 1]       = v01;
                        C32[(size_t)(gm0 + 8) * N + gn]     = v10;
                        C32[(size_t)(gm0 + 8) * N + gn + 1] = v11;
                    }
                }
                if (WF16) {
                    *(__half2*)&C16[(size_t)gm0 * N + gn]       = __floats2half2_rn(v00, v01);
                    *(__half2*)&C16[(size_t)(gm0 + 8) * N + gn] = __floats2half2_rn(v10, v11);
                }
            }
        }
    }
}

// ---------------- causal linear-attention scan, 8-step batched ----------------
__global__ __launch_bounds__(64)
void scan_kernel(const __half* __restrict__ Q, const __half* __restrict__ K,
                 const __half* __restrict__ V, __half* __restrict__ A)
{
    const int bh = blockIdx.x;
    const int b  = bh >> 3, h = bh & 7;
    const int m  = threadIdx.x;

    __shared__ float q_sh[8][64], k_sh[8][64], z_sh[64];

    float S[64];
#pragma unroll
    for (int d = 0; d < 64; d++) S[d] = 0.f;
    z_sh[m] = 0.f;

    const size_t stride = (size_t)BB * DM;
    const size_t base = (size_t)b * DM + h * 64 + m;

    float q[8], k[8], v[8];
#pragma unroll
    for (int s = 0; s < 8; s++) {
        size_t i = base + (size_t)s * stride;
        q[s] = __half2float(Q[i]);
        k[s] = __half2float(K[i]);
        v[s] = __half2float(V[i]);
    }

    for (int t0 = 0; t0 < TT; t0 += 8) {
#pragma unroll
        for (int s = 0; s < 8; s++) {
            q_sh[s][m] = q[s];
            k_sh[s][m] = k[s];
        }
        __syncthreads();

        float qn[8], kn[8], vn[8];
        if (t0 + 8 < TT) {
#pragma unroll
            for (int s = 0; s < 8; s++) {
                size_t i = base + (size_t)(t0 + 8 + s) * stride;
                qn[s] = __half2float(Q[i]);
                kn[s] = __half2float(K[i]);
                vn[s] = __half2float(V[i]);
            }
        }

        float num[8][2], den[8][2];
#pragma unroll
        for (int s = 0; s < 8; s++) {
            num[s][0] = 0.f; num[s][1] = 0.f;
            den[s][0] = 0.f; den[s][1] = 0.f;
        }

#pragma unroll 2
        for (int d0 = 0; d0 < 64; d0 += 4) {
            float4 zv = *(const float4*)&z_sh[d0];
            float zz[4] = { zv.x, zv.y, zv.z, zv.w };
#pragma unroll
            for (int s = 0; s < 8; s++) {
                float4 kk = *(const float4*)&k_sh[s][d0];
                float4 qq = *(const float4*)&q_sh[s][d0];
                const float* kf = (const float*)&kk;
                const float* qf = (const float*)&qq;
#pragma unroll
                for (int j = 0; j < 4; j++) {
                    const int d = d0 + j;
                    zz[j] += kf[j];
                    den[s][j & 1] = fmaf(qf[j], zz[j], den[s][j & 1]);
                    S[d] = fmaf(kf[j], v[s], S[d]);
                    num[s][j & 1] = fmaf(qf[j], S[d], num[s][j & 1]);
                }
            }
        }
        __syncthreads();

        z_sh[m] += ((k[0] + k[1]) + (k[2] + k[3])) + ((k[4] + k[5]) + (k[6] + k[7]));

#pragma unroll
        for (int s = 0; s < 8; s++) {
            float n  = num[s][0] + num[s][1];
            float dd = den[s][0] + den[s][1] + 1e-6f;
            A[base + (size_t)(t0 + s) * stride] = __float2half_rn(n / dd);
        }

#pragma unroll
        for (int s = 0; s < 8; s++) { q[s] = qn[s]; k[s] = kn[s]; v[s] = vn[s]; }
    }
}

// ---------------- fused residual + LayerNorm (fp16 residual branch) ----------------
__global__ __launch_bounds__(128)
void add_ln_kernel(float* __restrict__ H, __half* __restrict__ Hh,
                   const __half* __restrict__ R,
                   const float* __restrict__ g, const float* __restrict__ be)
{
    __shared__ float sh[4];
    const int n = blockIdx.x, tid = threadIdx.x;
    const size_t base = (size_t)n * DM;

    float x[4];
    float s = 0.f;
#pragma unroll
    for (int i = 0; i < 4; i++) {
        int d = tid + 128 * i;
        x[i] = H[base + d] + __half2float(R[base + d]);
        s += x[i];
    }
#pragma unroll
    for (int o = 16; o > 0; o >>= 1) s += __shfl_xor_sync(0xffffffffu, s, o);
    if ((tid & 31) == 0) sh[tid >> 5] = s;
    __syncthreads();
    float mean = (sh[0] + sh[1] + sh[2] + sh[3]) * (1.f / 512.f);
    __syncthreads();

    float vs = 0.f;
#pragma unroll
    for (int i = 0; i < 4; i++) { float dl = x[i] - mean; vs += dl * dl; }
#pragma unroll
    for (int o = 16; o > 0; o >>= 1) vs += __shfl_xor_sync(0xffffffffu, vs, o);
    if ((tid & 31) == 0) sh[tid >> 5] = vs;
    __syncthreads();
    float var = (sh[0] + sh[1] + sh[2] + sh[3]) * (1.f / 512.f);
    float inv = rsqrtf(var + 1e-5f);

#pragma unroll
    for (int i = 0; i < 4; i++) {
        int d = tid + 128 * i;
        float v = fmaf((x[i] - mean) * inv, g[d], be[d]);
        H[base + d] = v;
        Hh[base + d] = __float2half_rn(v);
    }
}

// ---------------- orchestration ----------------
extern "C" void kernel_launch(void* const* d_in, const int* in_sizes, int n_in,
                              void* d_out, int out_size)
{
    (void)in_sizes; (void)n_in; (void)out_size;
    const int*   x   = (const int*)d_in[0];
    const float* E   = (const float*)d_in[1];
    const float* Wq  = (const float*)d_in[2];  const float* bq  = (const float*)d_in[3];
    const float* Wk  = (const float*)d_in[4];  const float* bk  = (const float*)d_in[5];
    const float* Wv  = (const float*)d_in[6];  const float* bv  = (const float*)d_in[7];
    const float* Wo  = (const float*)d_in[8];  const float* bo  = (const float*)d_in[9];
    const float* g1  = (const float*)d_in[10]; const float* be1 = (const float*)d_in[11];
    const float* W1  = (const float*)d_in[12]; const float* b1  = (const float*)d_in[13];
    const float* W2  = (const float*)d_in[14]; const float* b2  = (const float*)d_in[15];
    const float* g2  = (const float*)d_in[16]; const float* be2 = (const float*)d_in[17];
    const float* Wp  = (const float*)d_in[18]; const float* bp  = (const float*)d_in[19];
    float* out = (float*)d_out;

    float  *pH;
    __half *pHh, *pQh, *pKh, *pVh, *pTh, *pAh, *pFh;
    __half *pWqh, *pWkh, *pWvh, *pWoh, *pW1h, *pW2h, *pWph;
    cudaGetSymbolAddress((void**)&pH,  g_H);
    cudaGetSymbolAddress((void**)&pHh, g_Hh);
    cudaGetSymbolAddress((void**)&pQh, g_Qh);
    cudaGetSymbolAddress((void**)&pKh, g_Kh);
    cudaGetSymbolAddress((void**)&pVh, g_Vh);
    cudaGetSymbolAddress((void**)&pTh, g_Th);
    cudaGetSymbolAddress((void**)&pAh, g_Ah);
    cudaGetSymbolAddress((void**)&pFh, g_Fh);
    cudaGetSymbolAddress((void**)&pWqh, g_Wqh);
    cudaGetSymbolAddress((void**)&pWkh, g_Wkh);
    cudaGetSymbolAddress((void**)&pWvh, g_Wvh);
    cudaGetSymbolAddress((void**)&pWoh, g_Woh);
    cudaGetSymbolAddress((void**)&pW1h, g_W1h);
    cudaGetSymbolAddress((void**)&pW2h, g_W2h);
    cudaGetSymbolAddress((void**)&pWph, g_Wph);

    f2h_a<<<dim3(NLAYERS * DM * DM / 4 / 256, 1, 4), 256>>>(Wq, Wk, Wv, Wo,
                                                            pWqh, pWkh, pWvh, pWoh);
    f2h_b<<<dim3(NLAYERS * DM * DFF / 4 / 256, 1, 3), 256>>>(W1, W2, Wp, pW1h, pW2h, pWph);

    embed_kernel<<<(NTOK * DM) / 256, 256>>>(x, E, pH, pHh);

    const dim3 gDM(DM / 128, NTOK / 128);     // (4, 512)
    const dim3 gFF(DFF / 128, NTOK / 128);    // (16, 512)
    const dim3 gP(1, NTOK / 128);             // (1, 512)

    for (int l = 0; l < NLAYERS; l++) {
        const size_t wOff  = (size_t)l * DM * DM;
        const size_t bOff  = (size_t)l * DM;
        const size_t w1Off = (size_t)l * DM * DFF;
        const size_t b1Off = (size_t)l * DFF;
        const size_t w2Off = (size_t)l * DFF * DM;

        hgemm<1,0,1,0><<<gDM, 512>>>(pHh, pWqh + wOff, bq + bOff, (float*)0, pQh, NTOK, DM, DM);
        hgemm<1,0,1,0><<<gDM, 512>>>(pHh, pWkh + wOff, bk + bOff, (float*)0, pKh, NTOK, DM, DM);
        hgemm<0,0,1,0><<<gDM, 512>>>(pHh, pWvh + wOff, bv + bOff, (float*)0, pVh, NTOK, DM, DM);

        scan_kernel<<<BB * NH, 64>>>(pQh, pKh, pVh, pAh);

        hgemm<0,0,1,0><<<gDM, 512>>>(pAh, pWoh + wOff, bo + bOff, (float*)0, pTh, NTOK, DM, DM);
        add_ln_kernel<<<NTOK, 128>>>(pH, pHh, pTh, g1 + bOff, be1 + bOff);

        hgemm<2,0,1,0><<<gFF, 512>>>(pHh, pW1h + w1Off, b1 + b1Off, (float*)0, pFh, NTOK, DFF, DM);
        hgemm<0,0,1,0><<<gDM, 512>>>(pFh, pW2h + w2Off, b2 + bOff, (float*)0, pTh, NTOK, DM, DFF);
        add_ln_kernel<<<NTOK, 128>>>(pH, pHh, pTh, g2 + bOff, be2 + bOff);
    }

    hgemm<0,1,0,1><<<gP, 512>>>(pHh, pWph, bp, out, (__half*)0, NTOK, NCLS, DM);
}